// round 15
// baseline (speedup 1.0000x reference)
#include <cuda_runtime.h>
#include <math.h>

#define BB 4
#define DD 128
#define HH 192
#define WW 192
#define HQ 176
#define WQ 176
#define KK 145
#define NPIX (BB*HQ*WQ)
#define S_SCORES (BB*HQ*WQ*KK)
#define S_MASK   (BB*HQ*WQ)

#define QS_STRIDE 68
#define FS_STRIDE 84
#define QS_SZ (DD*QS_STRIDE)
#define FS_SZ  (DD*FS_STRIDE)
#define SMEM_FLOATS (4*QS_SZ + 2*FS_SZ)
#define SMEM_BYTES  (SMEM_FLOATS*4 + 256*4)

// scratch: feat2 transposed [b][y][x][d], warped feat2 [b][y][d][x],
// transposed scores [k][pix]
__device__ float g_f2T[(size_t)BB*HH*WW*DD];
__device__ float g_f2to1[(size_t)BB*HH*DD*WW];
__device__ float g_scoresT[(size_t)KK*NPIX];

// ---------------- coord helpers (match reference exactly) -------------------
__device__ __forceinline__ void pixel_coords(float ax, float ay, float& sx, float& sy) {
    float gx = ax * (2.0f / (WW - 1)) - 1.0f;
    float gy = ay * (2.0f / (HH - 1)) - 1.0f;
    if (isnan(gx)) gx = 9e9f;
    if (isnan(gy)) gy = 9e9f;
    sx = ((gx + 1.0f) * WW - 1.0f) * 0.5f;
    sy = ((gy + 1.0f) * HH - 1.0f) * 0.5f;
}

struct Bilin { int o00,o01,o10,o11; float w00,w01,w10,w11; };

__device__ __forceinline__ Bilin make_bilin(float sx, float sy) {
    float x0f = floorf(sx), y0f = floorf(sy);
    float fx = sx - x0f, fy = sy - y0f;
    bool vx0 = (x0f >= 0.0f) && (x0f <= (float)(WW-1));
    bool vx1 = (x0f+1.0f >= 0.0f) && (x0f+1.0f <= (float)(WW-1));
    bool vy0 = (y0f >= 0.0f) && (y0f <= (float)(HH-1));
    bool vy1 = (y0f+1.0f >= 0.0f) && (y0f+1.0f <= (float)(HH-1));
    int xi0 = (int)fminf(fmaxf(x0f,        0.0f), (float)(WW-1));
    int xi1 = (int)fminf(fmaxf(x0f + 1.0f, 0.0f), (float)(WW-1));
    int yi0 = (int)fminf(fmaxf(y0f,        0.0f), (float)(HH-1));
    int yi1 = (int)fminf(fmaxf(y0f + 1.0f, 0.0f), (float)(HH-1));
    Bilin r;
    r.o00 = yi0*WW + xi0; r.o01 = yi0*WW + xi1;
    r.o10 = yi1*WW + xi0; r.o11 = yi1*WW + xi1;
    r.w00 = (vx0 && vy0) ? (1.0f-fx)*(1.0f-fy) : 0.0f;
    r.w01 = (vx1 && vy0) ? fx*(1.0f-fy)        : 0.0f;
    r.w10 = (vx0 && vy1) ? (1.0f-fx)*fy        : 0.0f;
    r.w11 = (vx1 && vy1) ? fx*fy               : 0.0f;
    return r;
}

// ---------------- cp.async helpers ------------------------------------------
__device__ __forceinline__ void cpasync16(void* dst, const void* src, int sz) {
    unsigned sa = (unsigned)__cvta_generic_to_shared(dst);
    asm volatile("cp.async.cg.shared.global [%0], [%1], 16, %2;"
                 :: "r"(sa), "l"(src), "r"(sz));
}
__device__ __forceinline__ void cpasync_commit() {
    asm volatile("cp.async.commit_group;");
}
template<int N>
__device__ __forceinline__ void cpasync_wait() {
    asm volatile("cp.async.wait_group %0;" :: "n"(N));
}

// ---------------- K0: transpose feat2 [b][d][y][x] -> g_f2T [b][y][x][d] ----
__global__ void __launch_bounds__(256) transposeF_kernel(const float* __restrict__ feat2)
{
    __shared__ float tile[32][33];
    int xt = blockIdx.x;
    int dt = blockIdx.y;
    int z  = blockIdx.z;
    int b = z / HH;
    int y = z - b*HH;
    int tid = threadIdx.x;

    {
        int lx = tid & 31, ld = tid >> 5;
        #pragma unroll
        for (int k = 0; k < 4; k++) {
            int d = k*8 + ld;
            tile[d][lx] = __ldg(&feat2[(((size_t)b*DD + dt*32 + d)*HH + y)*WW + xt*32 + lx]);
        }
    }
    __syncthreads();
    {
        int dd = tid & 31, lx = tid >> 5;
        #pragma unroll
        for (int k = 0; k < 4; k++) {
            int xx = k*8 + lx;
            g_f2T[((size_t)(b*HH + y)*WW + xt*32 + xx)*DD + dt*32 + dd] = tile[dd][xx];
        }
    }
}

// ---------------- K1a: bilinear warp (d-contiguous gather) ------------------
__global__ void __launch_bounds__(256) warp_feat_kernel(const float* __restrict__ aflow)
{
    __shared__ float tile[8][132];
    int bx = blockIdx.x, y = blockIdx.y, b = blockIdx.z;
    int tid = threadIdx.x, lane = tid & 31, pg = tid >> 5;
    int x = bx*8 + pg;

    float ax = __ldg(&aflow[((size_t)(b*2+0)*HH + y)*WW + x]);
    float ay = __ldg(&aflow[((size_t)(b*2+1)*HH + y)*WW + x]);
    float sx, sy; pixel_coords(ax, ay, sx, sy);
    Bilin bl = make_bilin(sx, sy);

    const float* fb = g_f2T + (size_t)b*HH*WW*DD;
    float4 c00 = __ldg(reinterpret_cast<const float4*>(fb + (size_t)bl.o00*DD) + lane);
    float4 c01 = __ldg(reinterpret_cast<const float4*>(fb + (size_t)bl.o01*DD) + lane);
    float4 c10 = __ldg(reinterpret_cast<const float4*>(fb + (size_t)bl.o10*DD) + lane);
    float4 c11 = __ldg(reinterpret_cast<const float4*>(fb + (size_t)bl.o11*DD) + lane);

    float4 acc;
    acc.x = bl.w00*c00.x + bl.w01*c01.x + bl.w10*c10.x + bl.w11*c11.x;
    acc.y = bl.w00*c00.y + bl.w01*c01.y + bl.w10*c10.y + bl.w11*c11.y;
    acc.z = bl.w00*c00.z + bl.w01*c01.z + bl.w10*c10.z + bl.w11*c11.z;
    acc.w = bl.w00*c00.w + bl.w01*c01.w + bl.w10*c10.w + bl.w11*c11.w;
    *reinterpret_cast<float4*>(&tile[pg][4*lane]) = acc;
    __syncthreads();

    float* outp = g_f2to1 + ((size_t)(b*HH + y))*DD*WW + bx*8;
    #pragma unroll
    for (int k = 0; k < 4; k++) {
        int i = tid + k*256;
        int d = i >> 3, px = i & 7;
        outp[(size_t)d*WW + px] = tile[px][d];
    }
}

// ---------------- K1b: mask2 + qconf ----------------------------------------
__global__ void __launch_bounds__(256) small_outputs_kernel(
    const float* __restrict__ conf1, const float* __restrict__ conf2,
    const float* __restrict__ aflow, float* __restrict__ out)
{
    int idx = blockIdx.x*256 + threadIdx.x;
    if (idx >= S_MASK) return;
    int b = idx / (HQ*WQ);
    int r = idx % (HQ*WQ);
    int h = r / WQ, w = r % WQ;
    int gy = 8 + h, gx = 8 + w;

    float ax = aflow[((size_t)(b*2+0)*HH + gy)*WW + gx];
    float ay = aflow[((size_t)(b*2+1)*HH + gy)*WW + gx];
    float sx, sy; pixel_coords(ax, ay, sx, sy);
    Bilin bl = make_bilin(sx, sy);

    const float* c2 = conf2 + (size_t)b*HH*WW;
    float c2to1 = bl.w00*c2[bl.o00] + bl.w01*c2[bl.o01]
                + bl.w10*c2[bl.o10] + bl.w11*c2[bl.o11];

    float nx = floorf(sx + 0.5f), ny = floorf(sy + 0.5f);
    float m = (nx >= 0.0f && nx <= (float)(WW-1) && ny >= 0.0f && ny <= (float)(HH-1))
                ? 1.0f : 0.0f;

    float c1v = conf1[((size_t)b*HH + gy)*WW + gx];
    out[(size_t)2*S_SCORES + idx] = m;
    out[(size_t)2*S_SCORES + S_MASK + idx] = 0.5f*(c1v + c2to1);
}

// ---------------- K2: correlation, 512 thr, 16-lane reduce-scatter ----------
// tz in [0,16): 8 channels each (d = tz + 16*kk). 4-stage butterfly:
// mask 8 -> rows A/B (lane bit3), mask 4 -> t-pair (bit2), mask 2 -> t (bit1),
// mask 1 -> duplicate full sum; even lanes store STG.32.
template<int DXLO, int ND>
__device__ __forceinline__ void corr2(const float* __restrict__ qrow,
    const float* __restrict__ frow,
    const int* __restrict__ kmA, const int* __restrict__ kmB,
    int pixA, int tx, int tz, bool wok)
{
    const int LO   = 8 + DXLO;
    const int LOW4 = LO & ~3;
    const int HI   = LO + 3 + ND - 1;
    const int N4   = (HI >> 2) - (LOW4 >> 2) + 1;
    const int BASE = LO - LOW4;

    float accA[4][ND], accB[4][ND];
    #pragma unroll
    for (int t = 0; t < 4; t++)
        #pragma unroll
        for (int u = 0; u < ND; u++) { accA[t][u] = 0.0f; accB[t][u] = 0.0f; }

    #pragma unroll
    for (int kk = 0; kk < 8; kk++) {
        int d = tz + (kk << 4);                    // stride-16 channel interleave
        float4 qa4 = *reinterpret_cast<const float4*>(&qrow[d*QS_STRIDE + 4*tx]);
        float4 qb4 = *reinterpret_cast<const float4*>(&qrow[QS_SZ + d*QS_STRIDE + 4*tx]);
        float qa[4] = {qa4.x, qa4.y, qa4.z, qa4.w};
        float qb[4] = {qb4.x, qb4.y, qb4.z, qb4.w};

        float fr[4*N4];
        const float* fp = &frow[d*FS_STRIDE + 4*tx + LOW4];
        #pragma unroll
        for (int c = 0; c < N4; c++) {
            float4 f4 = *reinterpret_cast<const float4*>(&fp[4*c]);
            fr[4*c+0] = f4.x; fr[4*c+1] = f4.y; fr[4*c+2] = f4.z; fr[4*c+3] = f4.w;
        }
        #pragma unroll
        for (int t = 0; t < 4; t++)
            #pragma unroll
            for (int u = 0; u < ND; u++) {
                float fv = fr[BASE + t + u];
                accA[t][u] = fmaf(qa[t], fv, accA[t][u]);
                accB[t][u] = fmaf(qb[t], fv, accB[t][u]);
            }
    }

    bool hi8 = (tz & 8) != 0;
    bool hi4 = (tz & 4) != 0;
    bool hi2 = (tz & 2) != 0;
    int trow = (tz >> 3) & 1;                       // 0 = row A, 1 = row B
    int tsel = ((tz & 4) ? 2 : 0) + ((tz & 2) ? 1 : 0);
    #pragma unroll
    for (int u = 0; u < ND; u++) {
        // stage 8: rows A/B across lane bit 3
        float w[4];
        #pragma unroll
        for (int t = 0; t < 4; t++) {
            float give = hi8 ? accA[t][u] : accB[t][u];
            float recv = __shfl_xor_sync(0xffffffffu, give, 8);
            w[t] = (hi8 ? accB[t][u] : accA[t][u]) + recv;
        }
        // stage 4: t-pairs across lane bit 2
        float z[2];
        #pragma unroll
        for (int j = 0; j < 2; j++) {
            float give = hi4 ? w[j] : w[j+2];
            float recv = __shfl_xor_sync(0xffffffffu, give, 4);
            z[j] = (hi4 ? w[j+2] : w[j]) + recv;
        }
        // stage 2: t within pair across lane bit 1
        float give = hi2 ? z[0] : z[1];
        float recv = __shfl_xor_sync(0xffffffffu, give, 2);
        float res = (hi2 ? z[1] : z[0]) + recv;
        // stage 1: final sum (both lanes of the pair hold it)
        res += __shfl_xor_sync(0xffffffffu, res, 1);

        int km = trow ? kmB[DXLO + 7 + u] : kmA[DXLO + 7 + u];
        if ((tz & 1) == 0 && km >= 0 && wok) {
            size_t off = (size_t)km*NPIX + pixA + trow*WQ + 4*tx + tsel;
            g_scoresT[off] = res;
        }
    }
}

__global__ void __launch_bounds__(512,1) corr_kernel(const float* __restrict__ feat1)
{
    extern __shared__ float sm[];
    float* qs   = sm;                        // [4 rows][128][68]
    float* fs   = sm + 4*QS_SZ;              // [2 slots][128][84]
    int*   kmap = (int*)(sm + SMEM_FLOATS);  // [17 dy rows][15 dx] incl sentinels

    int tid = threadIdx.x;
    int tz = tid & 15, tx = (tid >> 4) & 15, ty1 = tid >> 8;  // ty1 0..1
    int wb = blockIdx.x*64, h0 = blockIdx.y*4, b = blockIdx.z;

    // k-index map (dy,dx) -> output slot; dy rows -8..8 (|dy|=8 auto-invalid)
    if (tid < 255) {
        int j = tid/15 - 8, i = tid%15 - 7;
        int r2 = i*i + j*j, k = -1;
        if (r2 > 1 && r2 <= 49) {
            k = 1;
            for (int jj = -7; jj <= 7; jj++)
                for (int ii = -7; ii <= 7; ii++) {
                    if (jj > j || (jj == j && ii >= i)) continue;
                    int rr = ii*ii + jj*jj;
                    if (rr > 1 && rr <= 49) k++;
                }
        } else if (i == 0 && j == 0) k = 0;
        kmap[tid] = k;
    }

    // async f row stager into 2-slot ring (row r covers global y = h0+1+r)
    auto stage_f = [&](int r) {
        float* dst = fs + (r & 1)*FS_SZ;
        const float* src = g_f2to1 + (((size_t)b*HH + (h0 + 1 + r))*DD)*WW + wb;
        #pragma unroll
        for (int i = 0; i < 5; i++) {
            int idx = tid + i*512;
            int c = idx % 20, d = idx / 20;
            int sz = (wb + 4*c + 3 < WW) ? 16 : 0;
            const float* s = src + (size_t)d*WW + (sz ? 4*c : 0);
            cpasync16(&dst[d*FS_STRIDE + 4*c], s, sz);
        }
    };

    // prologue: q tile (4 rows, async) + f row 0
    {
        #pragma unroll
        for (int i = 0; i < 16; i++) {
            int idx = tid + i*512;
            int c = idx & 15, d = (idx >> 4) & 127, qr = idx >> 11;
            int xg = 8 + wb + 4*c;
            int sz = (xg + 3 < WW) ? 16 : 0;
            const float* s = feat1 + (((size_t)b*DD + d)*HH + (8 + h0 + qr))*WW + (sz ? xg : 0);
            cpasync16(&qs[(qr*DD + d)*QS_STRIDE + 4*c], s, sz);
        }
        stage_f(0);
        cpasync_commit();
    }

    int pixA = ((b*HQ + h0 + 2*ty1)*WQ) + wb;
    bool wok = (wb + 4*tx) < WQ;
    const float* qrow = &qs[(size_t)(2*ty1)*QS_SZ];

    for (int r = 0; r < 18; r++) {
        cpasync_wait<0>();          // own groups drained (incl. group for row r)
        __syncthreads();            // publish + protect slot (r+1)&1
        if (r + 1 < 18) stage_f(r + 1);
        cpasync_commit();

        int dyA = r - 7 - 2*ty1;    // row B has dyB = dyA - 1
        if (dyA >= -7 && dyA <= 8) {
            const float* frow = &fs[(r & 1)*FS_SZ];
            const int* kmA = &kmap[(dyA + 8)*15];
            const int* kmB = &kmap[(dyA + 7)*15];
            switch (dyA) {
                case -7: case 8:
                    corr2<0,1>(qrow, frow, kmA, kmB, pixA, tx, tz, wok);
                    break;
                case -6: case 7:   // U = 7
                    corr2<-3,7>(qrow, frow, kmA, kmB, pixA, tx, tz, wok);
                    break;
                case -5: case 6:   // U = 9 -> 5 + 4
                    corr2<-4,5>(qrow, frow, kmA, kmB, pixA, tx, tz, wok);
                    corr2< 1,4>(qrow, frow, kmA, kmB, pixA, tx, tz, wok);
                    break;
                case -4: case 5:   // U = 11 -> 6 + 5
                    corr2<-5,6>(qrow, frow, kmA, kmB, pixA, tx, tz, wok);
                    corr2< 1,5>(qrow, frow, kmA, kmB, pixA, tx, tz, wok);
                    break;
                case 0: case 1:    // U = 15 -> 8 + 7
                    corr2<-7,8>(qrow, frow, kmA, kmB, pixA, tx, tz, wok);
                    corr2< 1,7>(qrow, frow, kmA, kmB, pixA, tx, tz, wok);
                    break;
                default:           // U = 13 -> 7 + 6
                    corr2<-6,7>(qrow, frow, kmA, kmB, pixA, tx, tz, wok);
                    corr2< 1,6>(qrow, frow, kmA, kmB, pixA, tx, tz, wok);
                    break;
            }
        }
    }
}

// ---------------- K3: transpose scoresT -> out scores, fused gt -------------
__global__ void __launch_bounds__(256) transpose_kernel(float* __restrict__ out)
{
    __shared__ float tile[KK*68];
    int p0 = blockIdx.x*64;
    int tid = threadIdx.x;

    for (int e = tid; e < KK*16; e += 256) {
        int k = e >> 4, jj = e & 15;
        float4 v = *reinterpret_cast<const float4*>(&g_scoresT[(size_t)k*NPIX + p0 + 4*jj]);
        *reinterpret_cast<float4*>(&tile[k*68 + 4*jj]) = v;
    }
    __syncthreads();

    for (int e = tid; e < 64*KK; e += 256) {
        int j = e / KK, k = e - j*KK;
        size_t o = (size_t)(p0 + j)*KK + k;
        out[o] = tile[k*68 + j];
        out[(size_t)S_SCORES + o] = (k == 0) ? 1.0f : 0.0f;
    }
}

// ---------------- launch -----------------------------------------------------
extern "C" void kernel_launch(void* const* d_in, const int* in_sizes, int n_in,
                              void* d_out, int out_size)
{
    const float* feat1 = (const float*)d_in[0];
    const float* feat2 = (const float*)d_in[1];
    const float* conf1 = (const float*)d_in[2];
    const float* conf2 = (const float*)d_in[3];
    const float* aflow = (const float*)d_in[4];
    float* out = (float*)d_out;

    cudaFuncSetAttribute(corr_kernel,
        cudaFuncAttributeMaxDynamicSharedMemorySize, SMEM_BYTES);

    transposeF_kernel<<<dim3(6, 4, HH*BB), 256>>>(feat2);
    warp_feat_kernel<<<dim3(24, HH, BB), 256>>>(aflow);
    small_outputs_kernel<<<(S_MASK + 255)/256, 256>>>(conf1, conf2, aflow, out);
    corr_kernel<<<dim3(3, 44, BB), 512, SMEM_BYTES>>>(feat1);
    transpose_kernel<<<NPIX/64, 256>>>(out);
}

// round 17
// speedup vs baseline: 1.4145x; 1.4145x over previous
#include <cuda_runtime.h>
#include <math.h>

#define BB 4
#define DD 128
#define HH 192
#define WW 192
#define HQ 176
#define WQ 176
#define KK 145
#define NPIX (BB*HQ*WQ)
#define S_SCORES (BB*HQ*WQ*KK)
#define S_MASK   (BB*HQ*WQ)

#define QS_STRIDE 68
#define FS_STRIDE 84
#define QS_SZ (DD*QS_STRIDE)
#define FS_SZ  (DD*FS_STRIDE)
#define SMEM_FLOATS (4*QS_SZ + 2*FS_SZ)
#define SMEM_BYTES  (SMEM_FLOATS*4 + 256*4)

// scratch: feat2 transposed [b][y][x][d], warped feat2 [b][y][d][x],
// transposed scores [k][pix]
__device__ float g_f2T[(size_t)BB*HH*WW*DD];
__device__ float g_f2to1[(size_t)BB*HH*DD*WW];
__device__ float g_scoresT[(size_t)KK*NPIX];

// ---------------- coord helpers (match reference exactly) -------------------
__device__ __forceinline__ void pixel_coords(float ax, float ay, float& sx, float& sy) {
    float gx = ax * (2.0f / (WW - 1)) - 1.0f;
    float gy = ay * (2.0f / (HH - 1)) - 1.0f;
    if (isnan(gx)) gx = 9e9f;
    if (isnan(gy)) gy = 9e9f;
    sx = ((gx + 1.0f) * WW - 1.0f) * 0.5f;
    sy = ((gy + 1.0f) * HH - 1.0f) * 0.5f;
}

struct Bilin { int o00,o01,o10,o11; float w00,w01,w10,w11; };

__device__ __forceinline__ Bilin make_bilin(float sx, float sy) {
    float x0f = floorf(sx), y0f = floorf(sy);
    float fx = sx - x0f, fy = sy - y0f;
    bool vx0 = (x0f >= 0.0f) && (x0f <= (float)(WW-1));
    bool vx1 = (x0f+1.0f >= 0.0f) && (x0f+1.0f <= (float)(WW-1));
    bool vy0 = (y0f >= 0.0f) && (y0f <= (float)(HH-1));
    bool vy1 = (y0f+1.0f >= 0.0f) && (y0f+1.0f <= (float)(HH-1));
    int xi0 = (int)fminf(fmaxf(x0f,        0.0f), (float)(WW-1));
    int xi1 = (int)fminf(fmaxf(x0f + 1.0f, 0.0f), (float)(WW-1));
    int yi0 = (int)fminf(fmaxf(y0f,        0.0f), (float)(HH-1));
    int yi1 = (int)fminf(fmaxf(y0f + 1.0f, 0.0f), (float)(HH-1));
    Bilin r;
    r.o00 = yi0*WW + xi0; r.o01 = yi0*WW + xi1;
    r.o10 = yi1*WW + xi0; r.o11 = yi1*WW + xi1;
    r.w00 = (vx0 && vy0) ? (1.0f-fx)*(1.0f-fy) : 0.0f;
    r.w01 = (vx1 && vy0) ? fx*(1.0f-fy)        : 0.0f;
    r.w10 = (vx0 && vy1) ? (1.0f-fx)*fy        : 0.0f;
    r.w11 = (vx1 && vy1) ? fx*fy               : 0.0f;
    return r;
}

// ---------------- cp.async helpers ------------------------------------------
__device__ __forceinline__ void cpasync16(void* dst, const void* src, int sz) {
    unsigned sa = (unsigned)__cvta_generic_to_shared(dst);
    asm volatile("cp.async.cg.shared.global [%0], [%1], 16, %2;"
                 :: "r"(sa), "l"(src), "r"(sz));
}
__device__ __forceinline__ void cpasync_commit() {
    asm volatile("cp.async.commit_group;");
}
template<int N>
__device__ __forceinline__ void cpasync_wait() {
    asm volatile("cp.async.wait_group %0;" :: "n"(N));
}

// ---------------- K0: transpose feat2 [b][d][y][x] -> g_f2T [b][y][x][d] ----
__global__ void __launch_bounds__(256) transposeF_kernel(const float* __restrict__ feat2)
{
    __shared__ float tile[32][33];
    int xt = blockIdx.x;
    int dt = blockIdx.y;
    int z  = blockIdx.z;
    int b = z / HH;
    int y = z - b*HH;
    int tid = threadIdx.x;

    {
        int lx = tid & 31, ld = tid >> 5;
        #pragma unroll
        for (int k = 0; k < 4; k++) {
            int d = k*8 + ld;
            tile[d][lx] = __ldg(&feat2[(((size_t)b*DD + dt*32 + d)*HH + y)*WW + xt*32 + lx]);
        }
    }
    __syncthreads();
    {
        int dd = tid & 31, lx = tid >> 5;
        #pragma unroll
        for (int k = 0; k < 4; k++) {
            int xx = k*8 + lx;
            g_f2T[((size_t)(b*HH + y)*WW + xt*32 + xx)*DD + dt*32 + dd] = tile[dd][xx];
        }
    }
}

// ---------------- K1a: bilinear warp (d-contiguous gather) ------------------
__global__ void __launch_bounds__(256) warp_feat_kernel(const float* __restrict__ aflow)
{
    __shared__ float tile[8][132];
    int bx = blockIdx.x, y = blockIdx.y, b = blockIdx.z;
    int tid = threadIdx.x, lane = tid & 31, pg = tid >> 5;
    int x = bx*8 + pg;

    float ax = __ldg(&aflow[((size_t)(b*2+0)*HH + y)*WW + x]);
    float ay = __ldg(&aflow[((size_t)(b*2+1)*HH + y)*WW + x]);
    float sx, sy; pixel_coords(ax, ay, sx, sy);
    Bilin bl = make_bilin(sx, sy);

    const float* fb = g_f2T + (size_t)b*HH*WW*DD;
    float4 c00 = __ldg(reinterpret_cast<const float4*>(fb + (size_t)bl.o00*DD) + lane);
    float4 c01 = __ldg(reinterpret_cast<const float4*>(fb + (size_t)bl.o01*DD) + lane);
    float4 c10 = __ldg(reinterpret_cast<const float4*>(fb + (size_t)bl.o10*DD) + lane);
    float4 c11 = __ldg(reinterpret_cast<const float4*>(fb + (size_t)bl.o11*DD) + lane);

    float4 acc;
    acc.x = bl.w00*c00.x + bl.w01*c01.x + bl.w10*c10.x + bl.w11*c11.x;
    acc.y = bl.w00*c00.y + bl.w01*c01.y + bl.w10*c10.y + bl.w11*c11.y;
    acc.z = bl.w00*c00.z + bl.w01*c01.z + bl.w10*c10.z + bl.w11*c11.z;
    acc.w = bl.w00*c00.w + bl.w01*c01.w + bl.w10*c10.w + bl.w11*c11.w;
    *reinterpret_cast<float4*>(&tile[pg][4*lane]) = acc;
    __syncthreads();

    float* outp = g_f2to1 + ((size_t)(b*HH + y))*DD*WW + bx*8;
    #pragma unroll
    for (int k = 0; k < 4; k++) {
        int i = tid + k*256;
        int d = i >> 3, px = i & 7;
        outp[(size_t)d*WW + px] = tile[px][d];
    }
}

// ---------------- K1b: mask2 + qconf ----------------------------------------
__global__ void __launch_bounds__(256) small_outputs_kernel(
    const float* __restrict__ conf1, const float* __restrict__ conf2,
    const float* __restrict__ aflow, float* __restrict__ out)
{
    int idx = blockIdx.x*256 + threadIdx.x;
    if (idx >= S_MASK) return;
    int b = idx / (HQ*WQ);
    int r = idx % (HQ*WQ);
    int h = r / WQ, w = r % WQ;
    int gy = 8 + h, gx = 8 + w;

    float ax = aflow[((size_t)(b*2+0)*HH + gy)*WW + gx];
    float ay = aflow[((size_t)(b*2+1)*HH + gy)*WW + gx];
    float sx, sy; pixel_coords(ax, ay, sx, sy);
    Bilin bl = make_bilin(sx, sy);

    const float* c2 = conf2 + (size_t)b*HH*WW;
    float c2to1 = bl.w00*c2[bl.o00] + bl.w01*c2[bl.o01]
                + bl.w10*c2[bl.o10] + bl.w11*c2[bl.o11];

    float nx = floorf(sx + 0.5f), ny = floorf(sy + 0.5f);
    float m = (nx >= 0.0f && nx <= (float)(WW-1) && ny >= 0.0f && ny <= (float)(HH-1))
                ? 1.0f : 0.0f;

    float c1v = conf1[((size_t)b*HH + gy)*WW + gx];
    out[(size_t)2*S_SCORES + idx] = m;
    out[(size_t)2*S_SCORES + S_MASK + idx] = 0.5f*(c1v + c2to1);
}

// ---------------- K2: correlation, 2 query rows per thread (R14 version) ----
// Reduce-scatter butterfly over the 8 tz lanes: 7 shfl for all 8 (t,row)
// sums; lane tz ends holding (t = tz&3, row = tz>>2); single STG.32 per u.
template<int DXLO, int ND>
__device__ __forceinline__ void corr2(const float* __restrict__ qrow,
    const float* __restrict__ frow,
    const int* __restrict__ kmA, const int* __restrict__ kmB,
    int pixA, int tx, int tz, bool wok)
{
    const int LO   = 8 + DXLO;
    const int LOW4 = LO & ~3;
    const int HI   = LO + 3 + ND - 1;
    const int N4   = (HI >> 2) - (LOW4 >> 2) + 1;
    const int BASE = LO - LOW4;

    float accA[4][ND], accB[4][ND];
    #pragma unroll
    for (int t = 0; t < 4; t++)
        #pragma unroll
        for (int u = 0; u < ND; u++) { accA[t][u] = 0.0f; accB[t][u] = 0.0f; }

    #pragma unroll 4
    for (int kk = 0; kk < 16; kk++) {
        int d = tz + (kk << 3);                    // stride-8 channel interleave
        float4 qa4 = *reinterpret_cast<const float4*>(&qrow[d*QS_STRIDE + 4*tx]);
        float4 qb4 = *reinterpret_cast<const float4*>(&qrow[QS_SZ + d*QS_STRIDE + 4*tx]);
        float qa[4] = {qa4.x, qa4.y, qa4.z, qa4.w};
        float qb[4] = {qb4.x, qb4.y, qb4.z, qb4.w};

        float fr[4*N4];
        const float* fp = &frow[d*FS_STRIDE + 4*tx + LOW4];
        #pragma unroll
        for (int c = 0; c < N4; c++) {
            float4 f4 = *reinterpret_cast<const float4*>(&fp[4*c]);
            fr[4*c+0] = f4.x; fr[4*c+1] = f4.y; fr[4*c+2] = f4.z; fr[4*c+3] = f4.w;
        }
        #pragma unroll
        for (int t = 0; t < 4; t++)
            #pragma unroll
            for (int u = 0; u < ND; u++) {
                float fv = fr[BASE + t + u];
                accA[t][u] = fmaf(qa[t], fv, accA[t][u]);
                accB[t][u] = fmaf(qb[t], fv, accB[t][u]);
            }
    }

    bool hi4 = (tz & 4) != 0;
    bool hi2 = (tz & 2) != 0;
    bool hi1 = (tz & 1) != 0;
    #pragma unroll
    for (int u = 0; u < ND; u++) {
        float w[4];
        #pragma unroll
        for (int t = 0; t < 4; t++) {
            float give = hi4 ? accA[t][u] : accB[t][u];
            float recv = __shfl_xor_sync(0xffffffffu, give, 4);
            w[t] = (hi4 ? accB[t][u] : accA[t][u]) + recv;
        }
        float z[2];
        #pragma unroll
        for (int j = 0; j < 2; j++) {
            float give = hi2 ? w[j] : w[j+2];
            float recv = __shfl_xor_sync(0xffffffffu, give, 2);
            z[j] = (hi2 ? w[j+2] : w[j]) + recv;
        }
        float give = hi1 ? z[0] : z[1];
        float recv = __shfl_xor_sync(0xffffffffu, give, 1);
        float res = (hi1 ? z[1] : z[0]) + recv;

        int kA_ = kmA[DXLO + 7 + u];
        int kB_ = kmB[DXLO + 7 + u];
        int km = hi4 ? kB_ : kA_;
        if (km >= 0 && wok) {
            size_t off = (size_t)km*NPIX + pixA + (hi4 ? WQ : 0) + 4*tx + (tz & 3);
            g_scoresT[off] = res;
        }
    }
}

__global__ void __launch_bounds__(256,1) corr_kernel(const float* __restrict__ feat1)
{
    extern __shared__ float sm[];
    float* qs   = sm;                        // [4 rows][128][68]
    float* fs   = sm + 4*QS_SZ;              // [2 slots][128][84]
    int*   kmap = (int*)(sm + SMEM_FLOATS);  // [17 dy rows][15 dx] incl sentinels

    int tid = threadIdx.x;
    int tz = tid & 7, tx = (tid >> 3) & 15, ty1 = tid >> 7;  // ty1 0..1
    int wb = blockIdx.x*64, h0 = blockIdx.y*4, b = blockIdx.z;

    if (tid < 255) {
        int j = tid/15 - 8, i = tid%15 - 7;
        int r2 = i*i + j*j, k = -1;
        if (r2 > 1 && r2 <= 49) {
            k = 1;
            for (int jj = -7; jj <= 7; jj++)
                for (int ii = -7; ii <= 7; ii++) {
                    if (jj > j || (jj == j && ii >= i)) continue;
                    int rr = ii*ii + jj*jj;
                    if (rr > 1 && rr <= 49) k++;
                }
        } else if (i == 0 && j == 0) k = 0;
        kmap[tid] = k;
    }

    auto stage_f = [&](int r) {
        float* dst = fs + (r & 1)*FS_SZ;
        const float* src = g_f2to1 + (((size_t)b*HH + (h0 + 1 + r))*DD)*WW + wb;
        #pragma unroll
        for (int i = 0; i < 10; i++) {
            int idx = tid + i*256;
            int c = idx % 20, d = idx / 20;
            int sz = (wb + 4*c + 3 < WW) ? 16 : 0;
            const float* s = src + (size_t)d*WW + (sz ? 4*c : 0);
            cpasync16(&dst[d*FS_STRIDE + 4*c], s, sz);
        }
    };

    {
        #pragma unroll
        for (int i = 0; i < 32; i++) {
            int idx = tid + i*256;
            int c = idx & 15, d = (idx >> 4) & 127, qr = idx >> 11;
            int xg = 8 + wb + 4*c;
            int sz = (xg + 3 < WW) ? 16 : 0;
            const float* s = feat1 + (((size_t)b*DD + d)*HH + (8 + h0 + qr))*WW + (sz ? xg : 0);
            cpasync16(&qs[(qr*DD + d)*QS_STRIDE + 4*c], s, sz);
        }
        stage_f(0);
        cpasync_commit();
    }

    int pixA = ((b*HQ + h0 + 2*ty1)*WQ) + wb;
    bool wok = (wb + 4*tx) < WQ;
    const float* qrow = &qs[(size_t)(2*ty1)*QS_SZ];

    for (int r = 0; r < 18; r++) {
        cpasync_wait<0>();
        __syncthreads();
        if (r + 1 < 18) stage_f(r + 1);
        cpasync_commit();

        int dyA = r - 7 - 2*ty1;
        if (dyA >= -7 && dyA <= 8) {
            const float* frow = &fs[(r & 1)*FS_SZ];
            const int* kmA = &kmap[(dyA + 8)*15];
            const int* kmB = &kmap[(dyA + 7)*15];
            switch (dyA) {
                case -7: case 8:
                    corr2<0,1>(qrow, frow, kmA, kmB, pixA, tx, tz, wok); break;
                case -6: case 7:
                    corr2<-3,7>(qrow, frow, kmA, kmB, pixA, tx, tz, wok); break;
                case -5: case 6:
                    corr2<-4,9>(qrow, frow, kmA, kmB, pixA, tx, tz, wok); break;
                case -4: case 5:
                    corr2<-5,11>(qrow, frow, kmA, kmB, pixA, tx, tz, wok); break;
                case 0: case 1:
                    corr2<-7,8>(qrow, frow, kmA, kmB, pixA, tx, tz, wok);
                    corr2< 1,7>(qrow, frow, kmA, kmB, pixA, tx, tz, wok);
                    break;
                default:
                    corr2<-6,13>(qrow, frow, kmA, kmB, pixA, tx, tz, wok); break;
            }
        }
    }
}

// ---------------- K3: transpose scoresT -> out scores, fused gt -------------
// tile stride 69 (= 5 mod 32, coprime) -> conflict-free phase-2 reads.
// Phase-1 stores are scalar (stride 69 breaks float4 alignment).
__global__ void __launch_bounds__(256) transpose_kernel(float* __restrict__ out)
{
    __shared__ float tile[KK*69];
    int p0 = blockIdx.x*64;
    int tid = threadIdx.x;

    for (int e = tid; e < KK*16; e += 256) {
        int k = e >> 4, jj = e & 15;
        float4 v = *reinterpret_cast<const float4*>(&g_scoresT[(size_t)k*NPIX + p0 + 4*jj]);
        float* tp = &tile[k*69 + 4*jj];
        tp[0] = v.x; tp[1] = v.y; tp[2] = v.z; tp[3] = v.w;
    }
    __syncthreads();

    for (int e = tid; e < 64*KK; e += 256) {
        int j = e / KK, k = e - j*KK;
        size_t o = (size_t)(p0 + j)*KK + k;
        out[o] = tile[k*69 + j];
        out[(size_t)S_SCORES + o] = (k == 0) ? 1.0f : 0.0f;
    }
}

// ---------------- launch -----------------------------------------------------
extern "C" void kernel_launch(void* const* d_in, const int* in_sizes, int n_in,
                              void* d_out, int out_size)
{
    const float* feat1 = (const float*)d_in[0];
    const float* feat2 = (const float*)d_in[1];
    const float* conf1 = (const float*)d_in[2];
    const float* conf2 = (const float*)d_in[3];
    const float* aflow = (const float*)d_in[4];
    float* out = (float*)d_out;

    cudaFuncSetAttribute(corr_kernel,
        cudaFuncAttributeMaxDynamicSharedMemorySize, SMEM_BYTES);

    transposeF_kernel<<<dim3(6, 4, HH*BB), 256>>>(feat2);
    warp_feat_kernel<<<dim3(24, HH, BB), 256>>>(aflow);
    small_outputs_kernel<<<(S_MASK + 255)/256, 256>>>(conf1, conf2, aflow, out);
    corr_kernel<<<dim3(3, 44, BB), 256, SMEM_BYTES>>>(feat1);
    transpose_kernel<<<NPIX/64, 256>>>(out);
}